// round 5
// baseline (speedup 1.0000x reference)
#include <cuda_runtime.h>

#define N_NODES 100000
#define N_EDGES 3200000
#define F_IN    512
#define NH      16
#define NC      3

// ---------------- scratch (device globals; device-code references ONLY) -----
__device__ int   g_deg_out[N_NODES];
__device__ int   g_deg_in [N_NODES];
__device__ float g_norm_src[N_NODES];
__device__ float g_norm_dst[N_NODES];
__device__ int   g_row_start[N_NODES + 1];
__device__ int   g_cursor[N_NODES];
__device__ int   g_csr_src[N_EDGES];             // src ids grouped by dst
__device__ float g_h1[(size_t)N_NODES * NH];     // (feat@W1)*ns
__device__ float g_x [(size_t)N_NODES * NH];     // relu(agg1*nd+b1)*ns
__device__ float g_W2f[NH * NC];                 // W2 @ Wfc
__device__ float g_b2f[NC];                      // b2 @ Wfc + bfc
__device__ int   g_idx64;                        // 1 if indices are int64

// ---------------- index dtype detection (int64 vs int32) --------------------
__global__ void k_detect(const int* __restrict__ src_as_i32) {
    int any = 0;
    #pragma unroll
    for (int j = 0; j < 64; j++) any |= src_as_i32[2 * j + 1];
    g_idx64 = (any == 0) ? 1 : 0;
}

__device__ __forceinline__ int load_idx(const void* p, int i, int is64) {
    return is64 ? (int)((const long long*)p)[i] : ((const int*)p)[i];
}

// ---------------- zero degree/cursor arrays ----------------------------------
__global__ void k_zero() {
    int i = blockIdx.x * blockDim.x + threadIdx.x;
    if (i < N_NODES) { g_deg_out[i] = 0; g_deg_in[i] = 0; }
}

// ---------------- degree histograms (int atomics) ----------------------------
__global__ void k_hist(const void* __restrict__ src, const void* __restrict__ dst) {
    int i = blockIdx.x * blockDim.x + threadIdx.x;
    if (i >= N_EDGES) return;
    int is64 = g_idx64;
    int s = load_idx(src, i, is64);
    int d = load_idx(dst, i, is64);
    atomicAdd(&g_deg_out[s], 1);
    atomicAdd(&g_deg_in [d], 1);
}

__global__ void k_norm() {
    int i = blockIdx.x * blockDim.x + threadIdx.x;
    if (i >= N_NODES) return;
    g_norm_src[i] = rsqrtf(fmaxf((float)g_deg_out[i], 1.f));
    g_norm_dst[i] = rsqrtf(fmaxf((float)g_deg_in [i], 1.f));
}

// ---------------- exclusive scan of deg_in -> row_start (+ cursor copy) ------
// Single block, 1024 threads, 98-element sequential chunks + Hillis-Steele.
__global__ __launch_bounds__(1024)
void k_scan() {
    __shared__ int sp[1024];
    const int CH = (N_NODES + 1023) / 1024;      // 98
    int tid = threadIdx.x;
    int base = tid * CH;
    int end  = min(base + CH, N_NODES);

    int s = 0;
    for (int j = base; j < end; j++) s += g_deg_in[j];
    sp[tid] = s;
    __syncthreads();
    #pragma unroll
    for (int off = 1; off < 1024; off <<= 1) {
        int v = (tid >= off) ? sp[tid - off] : 0;
        __syncthreads();
        sp[tid] += v;
        __syncthreads();
    }
    int run = sp[tid] - s;                        // exclusive prefix
    for (int j = base; j < end; j++) {
        g_row_start[j] = run;
        g_cursor[j]    = run;
        run += g_deg_in[j];
    }
    if (tid == 0) g_row_start[N_NODES] = N_EDGES;
}

// ---------------- fill CSR: one int atomic per edge --------------------------
__global__ void k_fill(const void* __restrict__ src, const void* __restrict__ dst) {
    int i = blockIdx.x * blockDim.x + threadIdx.x;
    if (i >= N_EDGES) return;
    int is64 = g_idx64;
    int s = load_idx(src, i, is64);
    int d = load_idx(dst, i, is64);
    int slot = atomicAdd(&g_cursor[d], 1);
    g_csr_src[slot] = s;
}

// ---------------- GEMM1: h1 = (feat @ W1) * norm_src  [100000x512 @ 512x16] --
#define GB 128
#define KC 128
#define SMEM_GEMM ((F_IN * NH + GB * (KC + 4)) * 4)

__global__ __launch_bounds__(256, 2)
void k_gemm1(const float* __restrict__ feat, const float* __restrict__ W1) {
    extern __shared__ float smem[];
    float* sW = smem;                    // [512][16]
    float* sF = smem + F_IN * NH;        // [128][KC+4]

    const int tid = threadIdx.x;
    const int nl  = tid >> 1;
    const int oh  = tid & 1;
    const int n0  = blockIdx.x * GB;

    {
        const float4* W4 = (const float4*)W1;
        float4* sW4 = (float4*)sW;
        #pragma unroll
        for (int t = tid; t < F_IN * NH / 4; t += 256) sW4[t] = W4[t];
    }

    unsigned long long A0 = 0ull, A1 = 0ull, A2 = 0ull, A3 = 0ull;

    for (int kc = 0; kc < F_IN; kc += KC) {
        __syncthreads();
        {
            const float4* f4 = (const float4*)feat;
            #pragma unroll
            for (int t = tid; t < GB * (KC / 4); t += 256) {
                int node = t >> 5;
                int q    = t & 31;
                int n    = n0 + node;
                float4 v = make_float4(0.f, 0.f, 0.f, 0.f);
                if (n < N_NODES)
                    v = f4[(size_t)n * (F_IN / 4) + (kc >> 2) + q];
                *(float4*)&sF[node * (KC + 4) + q * 4] = v;
            }
        }
        __syncthreads();

        const float* frow = &sF[nl * (KC + 4)];
        #pragma unroll 4
        for (int kk = 0; kk < KC; kk++) {
            float f = frow[kk];
            unsigned long long fp;
            asm("mov.b64 %0, {%1, %1};" : "=l"(fp) : "f"(f));
            const float* wp = &sW[(kc + kk) * NH + oh * 8];
            ulonglong2 wa = *(const ulonglong2*)wp;
            ulonglong2 wb = *(const ulonglong2*)(wp + 4);
            asm("fma.rn.f32x2 %0, %1, %2, %0;" : "+l"(A0) : "l"(fp), "l"(wa.x));
            asm("fma.rn.f32x2 %0, %1, %2, %0;" : "+l"(A1) : "l"(fp), "l"(wa.y));
            asm("fma.rn.f32x2 %0, %1, %2, %0;" : "+l"(A2) : "l"(fp), "l"(wb.x));
            asm("fma.rn.f32x2 %0, %1, %2, %0;" : "+l"(A3) : "l"(fp), "l"(wb.y));
        }
    }

    int n = n0 + nl;
    if (n < N_NODES) {
        float ns = g_norm_src[n];
        float2 v0 = *(float2*)&A0, v1 = *(float2*)&A1;
        float2 v2 = *(float2*)&A2, v3 = *(float2*)&A3;
        float4* dst4 = (float4*)&g_h1[(size_t)n * NH + oh * 8];
        dst4[0] = make_float4(v0.x * ns, v0.y * ns, v1.x * ns, v1.y * ns);
        dst4[1] = make_float4(v2.x * ns, v2.y * ns, v3.x * ns, v3.y * ns);
    }
}

// ---------------- W2f = W2 @ Wfc [16x3], b2f = b2 @ Wfc + bfc ----------------
__global__ void k_w2f(const float* __restrict__ W2, const float* __restrict__ b2,
                      const float* __restrict__ Wfc, const float* __restrict__ bfc) {
    int t = threadIdx.x;
    if (t < NH * NC) {
        int h = t / NC, c = t % NC;
        float s = 0.f;
        #pragma unroll 8
        for (int k = 0; k < 128; k++) s = fmaf(W2[h * 128 + k], Wfc[k * NC + c], s);
        g_W2f[t] = s;
    } else if (t < NH * NC + NC) {
        int c = t - NH * NC;
        float s = bfc[c];
        #pragma unroll 8
        for (int k = 0; k < 128; k++) s = fmaf(b2[k], Wfc[k * NC + c], s);
        g_b2f[c] = s;
    }
}

// ---------------- warp-per-node pull aggregation + fused epilogues -----------
// Lane layout: q = lane&3 owns float4 quad q; e = lane>>2 strides edges by 8.
// Per edge-group the 4 q-lanes read 4 consecutive float4 (64B, coalesced).
__device__ __forceinline__ float4 warp_reduce8(float4 a) {
    // sum across the 8 edge groups (lanes differing in bits 2..4; q preserved)
    #pragma unroll
    for (int m = 4; m <= 16; m <<= 1) {
        a.x += __shfl_xor_sync(0xffffffffu, a.x, m);
        a.y += __shfl_xor_sync(0xffffffffu, a.y, m);
        a.z += __shfl_xor_sync(0xffffffffu, a.z, m);
        a.w += __shfl_xor_sync(0xffffffffu, a.w, m);
    }
    return a;
}

__global__ __launch_bounds__(256)
void k_gather1(const float* __restrict__ b1) {
    int warp = blockIdx.x * (blockDim.x >> 5) + (threadIdx.x >> 5);
    int lane = threadIdx.x & 31;
    if (warp >= N_NODES) return;
    int rs = g_row_start[warp];
    int re = g_row_start[warp + 1];
    int q  = lane & 3;
    float4 acc = make_float4(0.f, 0.f, 0.f, 0.f);
    #pragma unroll 2
    for (int j = rs + (lane >> 2); j < re; j += 8) {
        int s = g_csr_src[j];
        float4 v = __ldg((const float4*)(g_h1 + (size_t)s * NH) + q);
        acc.x += v.x; acc.y += v.y; acc.z += v.z; acc.w += v.w;
    }
    acc = warp_reduce8(acc);
    if (lane < 4) {
        float nd = g_norm_dst[warp];
        float ns = g_norm_src[warp];
        float4 b = __ldg((const float4*)b1 + q);
        float4 r;
        r.x = fmaxf(fmaf(acc.x, nd, b.x), 0.f) * ns;
        r.y = fmaxf(fmaf(acc.y, nd, b.y), 0.f) * ns;
        r.z = fmaxf(fmaf(acc.z, nd, b.z), 0.f) * ns;
        r.w = fmaxf(fmaf(acc.w, nd, b.w), 0.f) * ns;
        *((float4*)(g_x + (size_t)warp * NH) + q) = r;
    }
}

__global__ __launch_bounds__(256)
void k_gather2(float* __restrict__ out) {
    __shared__ float sw[NH * NC + NC];
    if (threadIdx.x < NH * NC + NC)
        sw[threadIdx.x] = (threadIdx.x < NH * NC) ? g_W2f[threadIdx.x]
                                                  : g_b2f[threadIdx.x - NH * NC];
    __syncthreads();
    int warp = blockIdx.x * (blockDim.x >> 5) + (threadIdx.x >> 5);
    int lane = threadIdx.x & 31;
    if (warp >= N_NODES) return;
    int rs = g_row_start[warp];
    int re = g_row_start[warp + 1];
    int q  = lane & 3;
    float4 acc = make_float4(0.f, 0.f, 0.f, 0.f);
    #pragma unroll 2
    for (int j = rs + (lane >> 2); j < re; j += 8) {
        int s = g_csr_src[j];
        float4 v = __ldg((const float4*)(g_x + (size_t)s * NH) + q);
        acc.x += v.x; acc.y += v.y; acc.z += v.z; acc.w += v.w;
    }
    acc = warp_reduce8(acc);
    // lanes 0..3 hold quads 0..3; fused 16x3 dot
    float s0, s1, s2;
    {
        int h0 = q * 4;
        s0 = acc.x * sw[(h0+0)*3+0] + acc.y * sw[(h0+1)*3+0]
           + acc.z * sw[(h0+2)*3+0] + acc.w * sw[(h0+3)*3+0];
        s1 = acc.x * sw[(h0+0)*3+1] + acc.y * sw[(h0+1)*3+1]
           + acc.z * sw[(h0+2)*3+1] + acc.w * sw[(h0+3)*3+1];
        s2 = acc.x * sw[(h0+0)*3+2] + acc.y * sw[(h0+1)*3+2]
           + acc.z * sw[(h0+2)*3+2] + acc.w * sw[(h0+3)*3+2];
    }
    #pragma unroll
    for (int m = 1; m <= 2; m <<= 1) {
        s0 += __shfl_xor_sync(0xffffffffu, s0, m);
        s1 += __shfl_xor_sync(0xffffffffu, s1, m);
        s2 += __shfl_xor_sync(0xffffffffu, s2, m);
    }
    if (lane == 0) {
        float nd = g_norm_dst[warp];
        out[(size_t)warp * 3 + 0] = fmaf(nd, s0, sw[48]);
        out[(size_t)warp * 3 + 1] = fmaf(nd, s1, sw[49]);
        out[(size_t)warp * 3 + 2] = fmaf(nd, s2, sw[50]);
    }
}

// ---------------- launch ------------------------------------------------------
extern "C" void kernel_launch(void* const* d_in, const int* in_sizes, int n_in,
                              void* d_out, int out_size) {
    const float* feat = (const float*)d_in[0];
    const void*  src  = d_in[1];
    const void*  dst  = d_in[2];
    const float* W1   = (const float*)d_in[3];
    const float* b1   = (const float*)d_in[4];
    const float* W2   = (const float*)d_in[5];
    const float* b2   = (const float*)d_in[6];
    const float* Wfc  = (const float*)d_in[7];
    const float* bfc  = (const float*)d_in[8];
    float* out = (float*)d_out;

    cudaFuncSetAttribute(k_gemm1, cudaFuncAttributeMaxDynamicSharedMemorySize,
                         SMEM_GEMM);

    const int EB = (N_EDGES + 255) / 256;            // 12500
    const int NB = (N_NODES + 255) / 256;            // 391
    const int WB = (N_NODES + 7) / 8;                // 12500 (8 warps/block)

    k_detect <<<1, 1>>>((const int*)src);
    k_zero   <<<NB, 256>>>();
    k_hist   <<<EB, 256>>>(src, dst);
    k_norm   <<<NB, 256>>>();
    k_scan   <<<1, 1024>>>();
    k_fill   <<<EB, 256>>>(src, dst);
    k_gemm1  <<<(N_NODES + GB - 1) / GB, 256, SMEM_GEMM>>>(feat, W1);
    k_gather1<<<WB, 256>>>(b1);
    k_w2f    <<<1, 64>>>(W2, b2, Wfc, bfc);
    k_gather2<<<WB, 256>>>(out);
}

// round 7
// speedup vs baseline: 1.6145x; 1.6145x over previous
#include <cuda_runtime.h>

#define N_NODES 100000
#define N_EDGES 3200000
#define F_IN    512
#define NH      16
#define NC      3

// ---------------- scratch (device globals; device-code references ONLY) -----
__device__ int   g_deg_out[N_NODES];
__device__ int   g_deg_in [N_NODES];
__device__ float g_norm_src[N_NODES];
__device__ float g_norm_dst[N_NODES];
__device__ float g_h1  [(size_t)N_NODES * NH];   // feat@W1 (unscaled, then *ns)
__device__ float g_agg1[(size_t)N_NODES * NH];
__device__ float g_y   [(size_t)N_NODES * 4];    // (relu(agg1*nd+b1)*ns)@W2f, padded
__device__ float g_agg2[(size_t)N_NODES * 4];
__device__ float g_W2f [NH * NC];                 // W2 @ Wfc
__device__ float g_b2f [NC];                      // b2 @ Wfc + bfc
__device__ int   g_idx64;                         // 1 if indices are int64

// ---------------- index dtype detection (int64 vs int32) --------------------
__global__ void k_detect(const int* __restrict__ src_as_i32) {
    int any = 0;
    #pragma unroll
    for (int j = 0; j < 64; j++) any |= src_as_i32[2 * j + 1];
    g_idx64 = (any == 0) ? 1 : 0;
}

__device__ __forceinline__ int load_idx(const void* p, int i, int is64) {
    return is64 ? (int)((const long long*)p)[i] : ((const int*)p)[i];
}

// ---------------- zero accumulators ------------------------------------------
__global__ void k_zero() {
    int i = blockIdx.x * blockDim.x + threadIdx.x;
    if (i < N_NODES * NH) g_agg1[i] = 0.f;
    if (i < N_NODES * 4)  g_agg2[i] = 0.f;
    if (i < N_NODES) { g_deg_out[i] = 0; g_deg_in[i] = 0; }
}

// ---------------- fused GEMM1 + degree histogram -----------------------------
// Grid = 3*GEMM_BLOCKS. blockIdx%3==0 -> GEMM tile (fma-pipe bound);
// else -> degree histogram over a grid-stride slice of edges (atomic bound).
// The two block flavors co-reside per SM and overlap pipes.
#define GB 128
#define KC 128
#define GEMM_BLOCKS ((N_NODES + GB - 1) / GB)        // 782
#define DEG_BLOCKS  (GEMM_BLOCKS * 2)                // 1564
#define SMEM_GEMM ((F_IN * NH + GB * (KC + 4)) * 4)

__global__ __launch_bounds__(256, 2)
void k_fused(const float* __restrict__ feat, const float* __restrict__ W1,
             const void* __restrict__ src, const void* __restrict__ dst) {
    const int bx = blockIdx.x;
    if (bx % 3 != 0) {
        // ---- degree path ----
        int db = (bx / 3) * 2 + (bx % 3) - 1;        // 0..DEG_BLOCKS-1
        int t  = db * 256 + threadIdx.x;
        const int STRIDE = DEG_BLOCKS * 256;
        int is64 = g_idx64;
        for (int i = t; i < N_EDGES; i += STRIDE) {
            int s = load_idx(src, i, is64);
            int d = load_idx(dst, i, is64);
            atomicAdd(&g_deg_out[s], 1);
            atomicAdd(&g_deg_in [d], 1);
        }
        return;
    }
    // ---- GEMM path ----
    extern __shared__ float smem[];
    float* sW = smem;                    // [512][16]
    float* sF = smem + F_IN * NH;        // [128][KC+4]

    const int tid = threadIdx.x;
    const int nl  = tid >> 1;
    const int oh  = tid & 1;
    const int n0  = (bx / 3) * GB;

    {
        const float4* W4 = (const float4*)W1;
        float4* sW4 = (float4*)sW;
        #pragma unroll
        for (int t = tid; t < F_IN * NH / 4; t += 256) sW4[t] = W4[t];
    }

    unsigned long long A0 = 0ull, A1 = 0ull, A2 = 0ull, A3 = 0ull;

    for (int kc = 0; kc < F_IN; kc += KC) {
        __syncthreads();
        {
            const float4* f4 = (const float4*)feat;
            #pragma unroll
            for (int t = tid; t < GB * (KC / 4); t += 256) {
                int node = t >> 5;
                int q    = t & 31;
                int n    = n0 + node;
                float4 v = make_float4(0.f, 0.f, 0.f, 0.f);
                if (n < N_NODES)
                    v = f4[(size_t)n * (F_IN / 4) + (kc >> 2) + q];
                *(float4*)&sF[node * (KC + 4) + q * 4] = v;
            }
        }
        __syncthreads();

        const float* frow = &sF[nl * (KC + 4)];
        #pragma unroll 4
        for (int kk = 0; kk < KC; kk++) {
            float f = frow[kk];
            unsigned long long fp;
            asm("mov.b64 %0, {%1, %1};" : "=l"(fp) : "f"(f));
            const float* wp = &sW[(kc + kk) * NH + oh * 8];
            ulonglong2 wa = *(const ulonglong2*)wp;
            ulonglong2 wb = *(const ulonglong2*)(wp + 4);
            asm("fma.rn.f32x2 %0, %1, %2, %0;" : "+l"(A0) : "l"(fp), "l"(wa.x));
            asm("fma.rn.f32x2 %0, %1, %2, %0;" : "+l"(A1) : "l"(fp), "l"(wa.y));
            asm("fma.rn.f32x2 %0, %1, %2, %0;" : "+l"(A2) : "l"(fp), "l"(wb.x));
            asm("fma.rn.f32x2 %0, %1, %2, %0;" : "+l"(A3) : "l"(fp), "l"(wb.y));
        }
    }

    int n = n0 + nl;
    if (n < N_NODES) {
        float2 v0 = *(float2*)&A0, v1 = *(float2*)&A1;
        float2 v2 = *(float2*)&A2, v3 = *(float2*)&A3;
        float4* dst4 = (float4*)&g_h1[(size_t)n * NH + oh * 8];
        dst4[0] = make_float4(v0.x, v0.y, v1.x, v1.y);
        dst4[1] = make_float4(v2.x, v2.y, v3.x, v3.y);
    }
}

// ---------------- norms + scale h1 rows by norm_src (vectorized) -------------
__global__ void k_norm() {
    int i = blockIdx.x * blockDim.x + threadIdx.x;   // one float4 of h1
    if (i >= N_NODES * 4) return;
    int n = i >> 2, q = i & 3;
    float ns = rsqrtf(fmaxf((float)g_deg_out[n], 1.f));
    if (q == 0) {
        g_norm_src[n] = ns;
        g_norm_dst[n] = rsqrtf(fmaxf((float)g_deg_in[n], 1.f));
    }
    float4 v = ((const float4*)g_h1)[i];
    v.x *= ns; v.y *= ns; v.z *= ns; v.w *= ns;
    ((float4*)g_h1)[i] = v;
}

// ---------------- edge pass 1: agg1[d] += h1[s]  (16 floats, 4x RED.128) -----
__device__ __forceinline__ void red4(float* p, float4 v) {
    asm volatile("red.global.add.v4.f32 [%0], {%1,%2,%3,%4};"
                 :: "l"(p), "f"(v.x), "f"(v.y), "f"(v.z), "f"(v.w) : "memory");
}

__global__ void k_edge1(const void* __restrict__ src, const void* __restrict__ dst) {
    int i = blockIdx.x * blockDim.x + threadIdx.x;
    if (i >= N_EDGES) return;
    int is64 = g_idx64;
    int s = load_idx(src, i, is64);
    int d = load_idx(dst, i, is64);
    const float4* t4 = (const float4*)(g_h1 + (size_t)s * NH);
    float4 v0 = __ldg(t4 + 0), v1 = __ldg(t4 + 1);
    float4 v2 = __ldg(t4 + 2), v3 = __ldg(t4 + 3);
    float* base = g_agg1 + (size_t)d * NH;
    red4(base + 0,  v0);
    red4(base + 4,  v1);
    red4(base + 8,  v2);
    red4(base + 12, v3);
}

// ---------------- W2f = W2 @ Wfc [16x3], b2f = b2 @ Wfc + bfc ----------------
__global__ void k_w2f(const float* __restrict__ W2, const float* __restrict__ b2,
                      const float* __restrict__ Wfc, const float* __restrict__ bfc) {
    int t = threadIdx.x;
    if (t < NH * NC) {
        int h = t / NC, c = t % NC;
        float s = 0.f;
        #pragma unroll 8
        for (int k = 0; k < 128; k++) s = fmaf(W2[h * 128 + k], Wfc[k * NC + c], s);
        g_W2f[t] = s;
    } else if (t < NH * NC + NC) {
        int c = t - NH * NC;
        float s = bfc[c];
        #pragma unroll 8
        for (int k = 0; k < 128; k++) s = fmaf(b2[k], Wfc[k * NC + c], s);
        g_b2f[c] = s;
    }
}

// ---------------- y = (relu(agg1*nd+b1)*ns) @ W2f  -> float4 (w=0) -----------
__global__ void k_y(const float* __restrict__ b1) {
    __shared__ float sw[NH * NC];
    if (threadIdx.x < NH * NC) sw[threadIdx.x] = g_W2f[threadIdx.x];
    __syncthreads();
    int n = blockIdx.x * blockDim.x + threadIdx.x;
    if (n >= N_NODES) return;
    const float4* a4 = (const float4*)(g_agg1 + (size_t)n * NH);
    float4 A[4] = {a4[0], a4[1], a4[2], a4[3]};
    const float* af = (const float*)A;
    float nd = g_norm_dst[n];
    float ns = g_norm_src[n];
    float s0 = 0.f, s1 = 0.f, s2 = 0.f;
    #pragma unroll
    for (int h = 0; h < NH; h++) {
        float x = fmaxf(fmaf(af[h], nd, __ldg(b1 + h)), 0.f) * ns;
        s0 = fmaf(x, sw[h * 3 + 0], s0);
        s1 = fmaf(x, sw[h * 3 + 1], s1);
        s2 = fmaf(x, sw[h * 3 + 2], s2);
    }
    ((float4*)g_y)[n] = make_float4(s0, s1, s2, 0.f);
}

// ---------------- edge pass 2: agg2[d] += y[s]  (1x RED.128) -----------------
__global__ void k_edge2(const void* __restrict__ src, const void* __restrict__ dst) {
    int i = blockIdx.x * blockDim.x + threadIdx.x;
    if (i >= N_EDGES) return;
    int is64 = g_idx64;
    int s = load_idx(src, i, is64);
    int d = load_idx(dst, i, is64);
    float4 v = __ldg((const float4*)g_y + s);
    red4(g_agg2 + (size_t)d * 4, v);
}

// ---------------- out = nd * agg2.xyz + b2f ----------------------------------
__global__ void k_out(float* __restrict__ out) {
    int n = blockIdx.x * blockDim.x + threadIdx.x;
    if (n >= N_NODES) return;
    float4 a = ((const float4*)g_agg2)[n];
    float nd = g_norm_dst[n];
    out[(size_t)n * 3 + 0] = fmaf(nd, a.x, g_b2f[0]);
    out[(size_t)n * 3 + 1] = fmaf(nd, a.y, g_b2f[1]);
    out[(size_t)n * 3 + 2] = fmaf(nd, a.z, g_b2f[2]);
}

// ---------------- launch ------------------------------------------------------
extern "C" void kernel_launch(void* const* d_in, const int* in_sizes, int n_in,
                              void* d_out, int out_size) {
    const float* feat = (const float*)d_in[0];
    const void*  src  = d_in[1];
    const void*  dst  = d_in[2];
    const float* W1   = (const float*)d_in[3];
    const float* b1   = (const float*)d_in[4];
    const float* W2   = (const float*)d_in[5];
    const float* b2   = (const float*)d_in[6];
    const float* Wfc  = (const float*)d_in[7];
    const float* bfc  = (const float*)d_in[8];
    float* out = (float*)d_out;

    cudaFuncSetAttribute(k_fused, cudaFuncAttributeMaxDynamicSharedMemorySize,
                         SMEM_GEMM);

    const int EB = (N_EDGES + 255) / 256;            // 12500
    const int NB = (N_NODES + 255) / 256;            // 391

    k_detect<<<1, 1>>>((const int*)src);
    k_w2f   <<<1, 64>>>(W2, b2, Wfc, bfc);
    k_zero  <<<(N_NODES * NH + 255) / 256, 256>>>();
    k_fused <<<GEMM_BLOCKS * 3, 256, SMEM_GEMM>>>(feat, W1, src, dst);
    k_norm  <<<(N_NODES * 4 + 255) / 256, 256>>>();
    k_edge1 <<<EB, 256>>>(src, dst);
    k_y     <<<NB, 256>>>(b1);
    k_edge2 <<<EB, 256>>>(src, dst);
    k_out   <<<NB, 256>>>(out);
}

// round 8
// speedup vs baseline: 1.7874x; 1.1071x over previous
#include <cuda_runtime.h>

#define N_NODES 100000
#define N_EDGES 3200000
#define F_IN    512
#define NH      16
#define NC      3

// ---------------- scratch (device globals; device-code references ONLY) -----
__device__ int   g_deg_out[N_NODES];
__device__ int   g_deg_in [N_NODES];
__device__ float g_norm_src[N_NODES];
__device__ float g_norm_dst[N_NODES];
__device__ float g_h1  [(size_t)N_NODES * NH];   // feat@W1 (unscaled, then *ns)
__device__ float g_agg1[(size_t)N_NODES * NH];
__device__ float g_y   [(size_t)N_NODES * 4];    // (relu(agg1*nd+b1)*ns)@W2f, padded
__device__ float g_agg2[(size_t)N_NODES * 4];
__device__ float g_W2f [NH * NC];                 // W2 @ Wfc
__device__ float g_b2f [NC];                      // b2 @ Wfc + bfc
__device__ int   g_idx64;                         // 1 if indices are int64

// ---------------- index dtype detection (int64 vs int32) --------------------
__global__ void k_detect(const int* __restrict__ src_as_i32) {
    int any = 0;
    #pragma unroll
    for (int j = 0; j < 64; j++) any |= src_as_i32[2 * j + 1];
    g_idx64 = (any == 0) ? 1 : 0;
}

__device__ __forceinline__ int load_idx(const void* p, int i, int is64) {
    return is64 ? (int)((const long long*)p)[i] : ((const int*)p)[i];
}

// ---------------- zero accumulators (runs on side stream) --------------------
__global__ void k_zero() {
    int i = blockIdx.x * blockDim.x + threadIdx.x;
    if (i < N_NODES * NH) g_agg1[i] = 0.f;
    if (i < N_NODES * 4)  g_agg2[i] = 0.f;
    if (i < N_NODES) { g_deg_out[i] = 0; g_deg_in[i] = 0; }
}

// ---------------- degree histogram (side stream, overlaps GEMM) -------------
__global__ __launch_bounds__(256)
void k_deg(const void* __restrict__ src, const void* __restrict__ dst) {
    int is64 = g_idx64;
    int stride = gridDim.x * blockDim.x;
    for (int i = blockIdx.x * blockDim.x + threadIdx.x; i < N_EDGES; i += stride) {
        int s = load_idx(src, i, is64);
        int d = load_idx(dst, i, is64);
        asm volatile("red.global.add.u32 [%0], %1;"
                     :: "l"(g_deg_out + s), "r"(1) : "memory");
        asm volatile("red.global.add.u32 [%0], %1;"
                     :: "l"(g_deg_in + d), "r"(1) : "memory");
    }
}

// ---------------- GEMM1: h1 = feat @ W1, cp.async double-buffered ------------
#define GB 128
#define KC 64
#define NCHUNK (F_IN / KC)                            // 8
#define SF_STRIDE (KC + 4)                            // 68 floats per node row
#define SF_ELEMS  (GB * SF_STRIDE)
#define SMEM_GEMM ((F_IN * NH + 2 * SF_ELEMS) * 4)    // 100 KB

__device__ __forceinline__ void stage_chunk(const float* __restrict__ feat,
                                            float* sF, int n0, int c, int tid) {
    #pragma unroll
    for (int t = tid; t < GB * (KC / 4); t += 256) {
        int node = t >> 4;                            // KC/4 == 16
        int q    = t & 15;
        int n    = n0 + node;
        const float* gsrc = feat +
            ((size_t)(n < N_NODES ? n : N_NODES - 1) * F_IN + c * KC + q * 4);
        int sz = (n < N_NODES) ? 16 : 0;              // 0 => zero-fill
        unsigned sa = (unsigned)__cvta_generic_to_shared(&sF[node * SF_STRIDE + q * 4]);
        asm volatile("cp.async.cg.shared.global [%0], [%1], 16, %2;"
                     :: "r"(sa), "l"(gsrc), "r"(sz) : "memory");
    }
    asm volatile("cp.async.commit_group;" ::: "memory");
}

__global__ __launch_bounds__(256, 2)
void k_gemm1(const float* __restrict__ feat, const float* __restrict__ W1) {
    extern __shared__ float smem[];
    float* sW  = smem;                                // [512][16]
    float* sF0 = smem + F_IN * NH;                    // 2 x [128][68]

    const int tid = threadIdx.x;
    const int nl  = tid >> 1;                         // local node 0..127
    const int oh  = tid & 1;                          // output half
    const int n0  = blockIdx.x * GB;

    {
        const float4* W4 = (const float4*)W1;
        float4* sW4 = (float4*)sW;
        #pragma unroll
        for (int t = tid; t < F_IN * NH / 4; t += 256) sW4[t] = W4[t];
    }

    stage_chunk(feat, sF0, n0, 0, tid);

    unsigned long long A0 = 0ull, A1 = 0ull, A2 = 0ull, A3 = 0ull;

    for (int c = 0; c < NCHUNK; c++) {
        if (c + 1 < NCHUNK) {
            stage_chunk(feat, sF0 + ((c + 1) & 1) * SF_ELEMS, n0, c + 1, tid);
            asm volatile("cp.async.wait_group 1;" ::: "memory");
        } else {
            asm volatile("cp.async.wait_group 0;" ::: "memory");
        }
        __syncthreads();

        const float* frow = sF0 + (c & 1) * SF_ELEMS + nl * SF_STRIDE;
        const float* wbase = sW + (size_t)c * KC * NH + oh * 8;
        #pragma unroll 4
        for (int kk = 0; kk < KC; kk++) {
            float f = frow[kk];
            unsigned long long fp;
            asm("mov.b64 %0, {%1, %1};" : "=l"(fp) : "f"(f));
            const float* wp = wbase + kk * NH;
            ulonglong2 wa = *(const ulonglong2*)wp;
            ulonglong2 wb = *(const ulonglong2*)(wp + 4);
            asm("fma.rn.f32x2 %0, %1, %2, %0;" : "+l"(A0) : "l"(fp), "l"(wa.x));
            asm("fma.rn.f32x2 %0, %1, %2, %0;" : "+l"(A1) : "l"(fp), "l"(wa.y));
            asm("fma.rn.f32x2 %0, %1, %2, %0;" : "+l"(A2) : "l"(fp), "l"(wb.x));
            asm("fma.rn.f32x2 %0, %1, %2, %0;" : "+l"(A3) : "l"(fp), "l"(wb.y));
        }
        __syncthreads();
    }

    int n = n0 + nl;
    if (n < N_NODES) {
        float2 v0 = *(float2*)&A0, v1 = *(float2*)&A1;
        float2 v2 = *(float2*)&A2, v3 = *(float2*)&A3;
        float4* dst4 = (float4*)&g_h1[(size_t)n * NH + oh * 8];
        dst4[0] = make_float4(v0.x, v0.y, v1.x, v1.y);
        dst4[1] = make_float4(v2.x, v2.y, v3.x, v3.y);
    }
}

// ---------------- norms + scale h1 rows by norm_src (vectorized) -------------
__global__ void k_norm() {
    int i = blockIdx.x * blockDim.x + threadIdx.x;   // one float4 of h1
    if (i >= N_NODES * 4) return;
    int n = i >> 2, q = i & 3;
    float ns = rsqrtf(fmaxf((float)g_deg_out[n], 1.f));
    if (q == 0) {
        g_norm_src[n] = ns;
        g_norm_dst[n] = rsqrtf(fmaxf((float)g_deg_in[n], 1.f));
    }
    float4 v = ((const float4*)g_h1)[i];
    v.x *= ns; v.y *= ns; v.z *= ns; v.w *= ns;
    ((float4*)g_h1)[i] = v;
}

// ---------------- edge pass 1: agg1[d] += h1[s]  (16 floats, 4x RED.128) -----
__device__ __forceinline__ void red4(float* p, float4 v) {
    asm volatile("red.global.add.v4.f32 [%0], {%1,%2,%3,%4};"
                 :: "l"(p), "f"(v.x), "f"(v.y), "f"(v.z), "f"(v.w) : "memory");
}

__global__ void k_edge1(const void* __restrict__ src, const void* __restrict__ dst) {
    int i = blockIdx.x * blockDim.x + threadIdx.x;
    if (i >= N_EDGES) return;
    int is64 = g_idx64;
    int s = load_idx(src, i, is64);
    int d = load_idx(dst, i, is64);
    const float4* t4 = (const float4*)(g_h1 + (size_t)s * NH);
    float4 v0 = __ldg(t4 + 0), v1 = __ldg(t4 + 1);
    float4 v2 = __ldg(t4 + 2), v3 = __ldg(t4 + 3);
    float* base = g_agg1 + (size_t)d * NH;
    red4(base + 0,  v0);
    red4(base + 4,  v1);
    red4(base + 8,  v2);
    red4(base + 12, v3);
}

// ---------------- W2f = W2 @ Wfc [16x3], b2f = b2 @ Wfc + bfc ----------------
__global__ void k_w2f(const float* __restrict__ W2, const float* __restrict__ b2,
                      const float* __restrict__ Wfc, const float* __restrict__ bfc) {
    int t = threadIdx.x;
    if (t < NH * NC) {
        int h = t / NC, c = t % NC;
        float s = 0.f;
        #pragma unroll 8
        for (int k = 0; k < 128; k++) s = fmaf(W2[h * 128 + k], Wfc[k * NC + c], s);
        g_W2f[t] = s;
    } else if (t < NH * NC + NC) {
        int c = t - NH * NC;
        float s = bfc[c];
        #pragma unroll 8
        for (int k = 0; k < 128; k++) s = fmaf(b2[k], Wfc[k * NC + c], s);
        g_b2f[c] = s;
    }
}

// ---------------- y = (relu(agg1*nd+b1)*ns) @ W2f  -> float4 (w=0) -----------
__global__ void k_y(const float* __restrict__ b1) {
    __shared__ float sw[NH * NC];
    if (threadIdx.x < NH * NC) sw[threadIdx.x] = g_W2f[threadIdx.x];
    __syncthreads();
    int n = blockIdx.x * blockDim.x + threadIdx.x;
    if (n >= N_NODES) return;
    const float4* a4 = (const float4*)(g_agg1 + (size_t)n * NH);
    float4 A[4] = {a4[0], a4[1], a4[2], a4[3]};
    const float* af = (const float*)A;
    float nd = g_norm_dst[n];
    float ns = g_norm_src[n];
    float s0 = 0.f, s1 = 0.f, s2 = 0.f;
    #pragma unroll
    for (int h = 0; h < NH; h++) {
        float x = fmaxf(fmaf(af[h], nd, __ldg(b1 + h)), 0.f) * ns;
        s0 = fmaf(x, sw[h * 3 + 0], s0);
        s1 = fmaf(x, sw[h * 3 + 1], s1);
        s2 = fmaf(x, sw[h * 3 + 2], s2);
    }
    ((float4*)g_y)[n] = make_float4(s0, s1, s2, 0.f);
}

// ---------------- edge pass 2: agg2[d] += y[s]  (1x RED.128) -----------------
__global__ void k_edge2(const void* __restrict__ src, const void* __restrict__ dst) {
    int i = blockIdx.x * blockDim.x + threadIdx.x;
    if (i >= N_EDGES) return;
    int is64 = g_idx64;
    int s = load_idx(src, i, is64);
    int d = load_idx(dst, i, is64);
    float4 v = __ldg((const float4*)g_y + s);
    red4(g_agg2 + (size_t)d * 4, v);
}

// ---------------- out = nd * agg2.xyz + b2f ----------------------------------
__global__ void k_out(float* __restrict__ out) {
    int n = blockIdx.x * blockDim.x + threadIdx.x;
    if (n >= N_NODES) return;
    float4 a = ((const float4*)g_agg2)[n];
    float nd = g_norm_dst[n];
    out[(size_t)n * 3 + 0] = fmaf(nd, a.x, g_b2f[0]);
    out[(size_t)n * 3 + 1] = fmaf(nd, a.y, g_b2f[1]);
    out[(size_t)n * 3 + 2] = fmaf(nd, a.z, g_b2f[2]);
}

// ---------------- launch ------------------------------------------------------
extern "C" void kernel_launch(void* const* d_in, const int* in_sizes, int n_in,
                              void* d_out, int out_size) {
    const float* feat = (const float*)d_in[0];
    const void*  src  = d_in[1];
    const void*  dst  = d_in[2];
    const float* W1   = (const float*)d_in[3];
    const float* b1   = (const float*)d_in[4];
    const float* W2   = (const float*)d_in[5];
    const float* b2   = (const float*)d_in[6];
    const float* Wfc  = (const float*)d_in[7];
    const float* bfc  = (const float*)d_in[8];
    float* out = (float*)d_out;

    static cudaStream_t s1 = nullptr;
    static cudaEvent_t  e0 = nullptr, e1 = nullptr;
    if (!s1) {
        cudaStreamCreateWithFlags(&s1, cudaStreamNonBlocking);
        cudaEventCreateWithFlags(&e0, cudaEventDisableTiming);
        cudaEventCreateWithFlags(&e1, cudaEventDisableTiming);
        cudaFuncSetAttribute(k_gemm1, cudaFuncAttributeMaxDynamicSharedMemorySize,
                             SMEM_GEMM);
    }

    const int EB = (N_EDGES + 255) / 256;            // 12500
    const int NB = (N_NODES + 255) / 256;            // 391

    // main stream: detect -> (fork) -> gemm1 (long)
    k_detect<<<1, 1>>>((const int*)src);
    cudaEventRecord(e0, 0);

    // side stream: zero + degree histogram + tiny W2f, overlapped with gemm1
    cudaStreamWaitEvent(s1, e0, 0);
    k_zero<<<(N_NODES * NH + 255) / 256, 256, 0, s1>>>();
    k_deg <<<2048, 256, 0, s1>>>(src, dst);
    k_w2f <<<1, 64, 0, s1>>>(W2, b2, Wfc, bfc);
    cudaEventRecord(e1, s1);

    // main stream continues
    k_gemm1<<<(N_NODES + GB - 1) / GB, 256, SMEM_GEMM>>>(feat, W1);
    cudaStreamWaitEvent(0, e1, 0);
    k_norm <<<(N_NODES * 4 + 255) / 256, 256>>>();
    k_edge1<<<EB, 256>>>(src, dst);
    k_y    <<<NB, 256>>>(b1);
    k_edge2<<<EB, 256>>>(src, dst);
    k_out  <<<NB, 256>>>(out);
}